// round 8
// baseline (speedup 1.0000x reference)
#include <cuda_runtime.h>
#include <cstdint>

// Problem constants (fixed by the dataset)
#define MAXN   50048
#define MAXE   800000
#define DIN    256
#define DH     256
#define DOUT   64
#define SCAN_B 1024

// Scratch (static device globals — no allocation allowed).
__device__ float g_bufA[MAXN * DH];     // GEMM output, pre-scaled by dis[row]
__device__ float g_bufB[MAXN * DH];     // aggregation output / next-layer input
__device__ float g_dis[MAXN];           // deg^{-1/2}
__device__ int   g_cnt[MAXN];           // degree count, then fill cursor
__device__ int   g_rowp[MAXN + 1];      // CSR row pointer
__device__ int   g_blk[128];            // block sums for scan
__device__ int   g_csrc[MAXE];          // CSR src indices

__device__ __forceinline__ float tf32_rna(float x) {
    uint32_t r;
    asm("cvt.rna.tf32.f32 %0, %1;" : "=r"(r) : "f"(x));
    return __uint_as_float(r);
}

#define MMA_TF32(D, Ar, Br) \
    asm volatile("mma.sync.aligned.m16n8k8.row.col.f32.tf32.tf32.f32 " \
        "{%0,%1,%2,%3}, {%4,%5,%6,%7}, {%8,%9}, {%0,%1,%2,%3};" \
        : "+f"((D)[0]), "+f"((D)[1]), "+f"((D)[2]), "+f"((D)[3]) \
        : "r"((Ar)[0]), "r"((Ar)[1]), "r"((Ar)[2]), "r"((Ar)[3]), \
          "r"((Br)[0]), "r"((Br)[1]))

// ===========================================================================
// CSR build + normalization
// ===========================================================================
__global__ void k_zero_cnt(int n) {
    int i = blockIdx.x * blockDim.x + threadIdx.x;
    if (i < n) g_cnt[i] = 0;
}

__global__ void k_count(const int* __restrict__ dst, int E, int n) {
    int e = blockIdx.x * blockDim.x + threadIdx.x;
    if (e < E) {
        unsigned d = (unsigned)dst[e];
        if (d < (unsigned)n) atomicAdd(&g_cnt[d], 1);
    }
}

// Inclusive scan within blocks; also computes dis = rsqrt(deg+1) (fused).
__global__ void k_scan1(int n) {
    __shared__ int sh[SCAN_B];
    int i = blockIdx.x * SCAN_B + threadIdx.x;
    int v = (i < n) ? g_cnt[i] : 0;
    if (i < n) g_dis[i] = rsqrtf((float)(v + 1));
    sh[threadIdx.x] = v;
    __syncthreads();
    #pragma unroll
    for (int off = 1; off < SCAN_B; off <<= 1) {
        int t = (threadIdx.x >= off) ? sh[threadIdx.x - off] : 0;
        __syncthreads();
        sh[threadIdx.x] += t;
        __syncthreads();
    }
    if (i < n) g_rowp[i + 1] = sh[threadIdx.x];
    if (threadIdx.x == SCAN_B - 1) g_blk[blockIdx.x] = sh[SCAN_B - 1];
}

__global__ void k_scan2(int nb) {
    __shared__ int sh[128];
    int v = (threadIdx.x < nb) ? g_blk[threadIdx.x] : 0;
    sh[threadIdx.x] = v;
    __syncthreads();
    #pragma unroll
    for (int off = 1; off < 128; off <<= 1) {
        int t = (threadIdx.x >= off) ? sh[threadIdx.x - off] : 0;
        __syncthreads();
        sh[threadIdx.x] += t;
        __syncthreads();
    }
    if (threadIdx.x < nb)
        g_blk[threadIdx.x] = (threadIdx.x > 0) ? sh[threadIdx.x - 1] : 0;
}

__global__ void k_scan3(int n) {
    int i = blockIdx.x * blockDim.x + threadIdx.x;
    if (i < n) {
        g_rowp[i + 1] += g_blk[i / SCAN_B];
        g_cnt[i] = 0;
    }
    if (i == 0) g_rowp[0] = 0;
}

__global__ void k_fill(const int* __restrict__ src, const int* __restrict__ dst,
                       int E, int n) {
    int e = blockIdx.x * blockDim.x + threadIdx.x;
    if (e >= E) return;
    unsigned s = (unsigned)src[e];
    unsigned d = (unsigned)dst[e];
    if (s >= (unsigned)n || d >= (unsigned)n) return;
    int pos = g_rowp[d] + atomicAdd(&g_cnt[d], 1);
    if (pos < MAXE) g_csrc[pos] = (int)s;
}

// ===========================================================================
// tf32 mma.sync GEMM: g_bufA[M,Nc] = (A[M,256] @ W[256,Nc]) * dis[row]
// Block tile 128x64, 8 warps (4x2), warp tile 32x32 (2x4 of m16n8k8), BK=32.
// ===========================================================================
__global__ __launch_bounds__(256) void k_gemm_mma(
    const float* __restrict__ A_ext, int useExt,
    const float* __restrict__ W, int M, int Nc)
{
    const float* __restrict__ A = useExt ? A_ext : (const float*)g_bufB;

    __shared__ float As[128][40];   // [m][k], pad 8 -> frag bank = 8*gid+tig
    __shared__ float Bs[32][72];    // [k][n], pad 8 -> frag bank = 8*tig+gid

    const int tid = threadIdx.x;
    const int lane = tid & 31;
    const int wid = tid >> 5;
    const int wm = wid & 3;          // 0..3 (M dir)
    const int wn = wid >> 2;         // 0..1 (N dir)
    const int gid = lane >> 2;
    const int tig = lane & 3;
    const int rowBase = blockIdx.y * 128;
    const int colBase = blockIdx.x * 64;

    const int la_row = tid >> 3;          // +32 per i
    const int la_c4  = tid & 7;
    const int lb_k  = tid >> 4;           // +16 per i
    const int lb_c4 = tid & 15;

    float acc[2][4][4];
    #pragma unroll
    for (int mt = 0; mt < 2; mt++)
        #pragma unroll
        for (int nt = 0; nt < 4; nt++)
            #pragma unroll
            for (int j = 0; j < 4; j++) acc[mt][nt][j] = 0.0f;

    float4 pa[4], pb[2];

    #pragma unroll
    for (int i = 0; i < 4; i++) {
        int grow = rowBase + la_row + i * 32;
        pa[i] = (grow < M) ? ((const float4*)A)[(long long)grow * 64 + la_c4]
                           : make_float4(0.f, 0.f, 0.f, 0.f);
    }
    #pragma unroll
    for (int i = 0; i < 2; i++) {
        int k = lb_k + i * 16;
        pb[i] = *(const float4*)(W + (long long)k * Nc + colBase + lb_c4 * 4);
    }

    #pragma unroll 1
    for (int kb = 0; kb < 8; kb++) {
        #pragma unroll
        for (int i = 0; i < 4; i++) {
            float4 v = pa[i];
            v.x = tf32_rna(v.x); v.y = tf32_rna(v.y);
            v.z = tf32_rna(v.z); v.w = tf32_rna(v.w);
            *(float4*)&As[la_row + i * 32][la_c4 * 4] = v;
        }
        #pragma unroll
        for (int i = 0; i < 2; i++) {
            float4 v = pb[i];
            v.x = tf32_rna(v.x); v.y = tf32_rna(v.y);
            v.z = tf32_rna(v.z); v.w = tf32_rna(v.w);
            *(float4*)&Bs[lb_k + i * 16][lb_c4 * 4] = v;
        }
        __syncthreads();

        if (kb < 7) {
            #pragma unroll
            for (int i = 0; i < 4; i++) {
                int grow = rowBase + la_row + i * 32;
                pa[i] = (grow < M)
                    ? ((const float4*)A)[(long long)grow * 64 + (kb + 1) * 8 + la_c4]
                    : make_float4(0.f, 0.f, 0.f, 0.f);
            }
            #pragma unroll
            for (int i = 0; i < 2; i++) {
                int k = (kb + 1) * 32 + lb_k + i * 16;
                pb[i] = *(const float4*)(W + (long long)k * Nc + colBase + lb_c4 * 4);
            }
        }

        #pragma unroll
        for (int ks = 0; ks < 4; ks++) {
            int k0 = ks * 8;
            uint32_t af[2][4], bf[4][2];
            #pragma unroll
            for (int mt = 0; mt < 2; mt++) {
                int m0 = wm * 32 + mt * 16 + gid;
                af[mt][0] = __float_as_uint(As[m0][k0 + tig]);
                af[mt][1] = __float_as_uint(As[m0 + 8][k0 + tig]);
                af[mt][2] = __float_as_uint(As[m0][k0 + tig + 4]);
                af[mt][3] = __float_as_uint(As[m0 + 8][k0 + tig + 4]);
            }
            #pragma unroll
            for (int nt = 0; nt < 4; nt++) {
                int n0 = wn * 32 + nt * 8 + gid;
                bf[nt][0] = __float_as_uint(Bs[k0 + tig][n0]);
                bf[nt][1] = __float_as_uint(Bs[k0 + tig + 4][n0]);
            }
            #pragma unroll
            for (int mt = 0; mt < 2; mt++)
                #pragma unroll
                for (int nt = 0; nt < 4; nt++)
                    MMA_TF32(acc[mt][nt], af[mt], bf[nt]);
        }
        __syncthreads();
    }

    #pragma unroll
    for (int mt = 0; mt < 2; mt++) {
        int r0 = rowBase + wm * 32 + mt * 16 + gid;
        int r1 = r0 + 8;
        float s0 = (r0 < M) ? g_dis[r0] : 0.f;
        float s1 = (r1 < M) ? g_dis[r1] : 0.f;
        #pragma unroll
        for (int nt = 0; nt < 4; nt++) {
            int c = colBase + wn * 32 + nt * 8 + tig * 2;
            if (r0 < M) {
                float2 o = make_float2(acc[mt][nt][0] * s0, acc[mt][nt][1] * s0);
                *(float2*)(g_bufA + (long long)r0 * Nc + c) = o;
            }
            if (r1 < M) {
                float2 o = make_float2(acc[mt][nt][2] * s1, acc[mt][nt][3] * s1);
                *(float2*)(g_bufA + (long long)r1 * Nc + c) = o;
            }
        }
    }
}

// ===========================================================================
// CSR gather aggregation (fused self-loop + bias + relu)
// F = feature width, VPT = float4 per thread. Lanes per node = F/(4*VPT).
// Unrolled x4 over neighbors: 4*VPT independent row loads in flight.
// ===========================================================================
template <int F, int VPT>
__global__ __launch_bounds__(256) void k_gather(
    float4* __restrict__ dst_ext, int useExt,
    const float* __restrict__ bias, int do_relu, int n)
{
    const int L = F / (4 * VPT);                 // lanes per node
    const int F4 = F / 4;
    float4* __restrict__ out = useExt ? dst_ext : (float4*)g_bufB;
    const float4* __restrict__ hs = (const float4*)g_bufA;

    int node = blockIdx.x * (256 / L) + threadIdx.x / L;
    if (node >= n) return;
    int lane = threadIdx.x % L;

    float4 acc[VPT];
    #pragma unroll
    for (int v = 0; v < VPT; v++)
        acc[v] = hs[(long long)node * F4 + lane + v * L];   // self term

    int p0 = g_rowp[node], p1 = g_rowp[node + 1];
    int p = p0;
    for (; p + 3 < p1; p += 4) {
        int s0 = g_csrc[p + 0];
        int s1 = g_csrc[p + 1];
        int s2 = g_csrc[p + 2];
        int s3 = g_csrc[p + 3];
        float4 t0[VPT], t1[VPT], t2[VPT], t3[VPT];
        #pragma unroll
        for (int v = 0; v < VPT; v++) {
            t0[v] = hs[(long long)s0 * F4 + lane + v * L];
            t1[v] = hs[(long long)s1 * F4 + lane + v * L];
            t2[v] = hs[(long long)s2 * F4 + lane + v * L];
            t3[v] = hs[(long long)s3 * F4 + lane + v * L];
        }
        #pragma unroll
        for (int v = 0; v < VPT; v++) {
            acc[v].x += (t0[v].x + t1[v].x) + (t2[v].x + t3[v].x);
            acc[v].y += (t0[v].y + t1[v].y) + (t2[v].y + t3[v].y);
            acc[v].z += (t0[v].z + t1[v].z) + (t2[v].z + t3[v].z);
            acc[v].w += (t0[v].w + t1[v].w) + (t2[v].w + t3[v].w);
        }
    }
    for (; p < p1; p++) {
        int s = g_csrc[p];
        #pragma unroll
        for (int v = 0; v < VPT; v++) {
            float4 t = hs[(long long)s * F4 + lane + v * L];
            acc[v].x += t.x; acc[v].y += t.y; acc[v].z += t.z; acc[v].w += t.w;
        }
    }

    float dd = g_dis[node];
    #pragma unroll
    for (int v = 0; v < VPT; v++) {
        float4 b4 = ((const float4*)bias)[lane + v * L];
        float4 o;
        o.x = acc[v].x * dd + b4.x;
        o.y = acc[v].y * dd + b4.y;
        o.z = acc[v].z * dd + b4.z;
        o.w = acc[v].w * dd + b4.w;
        if (do_relu) {
            o.x = fmaxf(o.x, 0.0f); o.y = fmaxf(o.y, 0.0f);
            o.z = fmaxf(o.z, 0.0f); o.w = fmaxf(o.w, 0.0f);
        }
        out[(long long)node * F4 + lane + v * L] = o;
    }
}

// ===========================================================================
// Launch
// ===========================================================================
extern "C" void kernel_launch(void* const* d_in, const int* in_sizes, int n_in,
                              void* d_out, int out_size)
{
    const float* x   = (const float*)d_in[0];
    const int*   ei  = (const int*)d_in[1];
    const float* W1  = (const float*)d_in[2];
    const float* b1  = (const float*)d_in[3];
    const float* W2  = (const float*)d_in[4];
    const float* b2  = (const float*)d_in[5];
    const float* W3  = (const float*)d_in[6];
    const float* b3  = (const float*)d_in[7];
    float*       out = (float*)d_out;

    const int N = in_sizes[0] / DIN;
    const int E = in_sizes[1] / 2;
    const int* srcp = ei;
    const int* dstp = ei + E;

    int mtiles = (N + 127) / 128;
    int nb = (N + SCAN_B - 1) / SCAN_B;

    // --- CSR build (launches 1-5) ---
    k_zero_cnt<<<(N + 255) / 256, 256>>>(N);                  // 1
    k_count<<<(E + 255) / 256, 256>>>(dstp, E, N);            // 2
    k_scan1<<<nb, SCAN_B>>>(N);                               // 3 (+dis fused)
    k_scan2<<<1, 128>>>(nb);                                  // 4
    k_scan3<<<(N + 255) / 256, 256>>>(N);                     // 5

    // ===== Layer 1 GEMM as launch #6 (profiled by ncu -s 5 -c 1) =====
    {
        dim3 grid(DH / 64, mtiles);
        k_gemm_mma<<<grid, 256>>>(x, 1, W1, N, DH);           // 6
    }
    // CSR fill (independent of GEMM; must precede gather-1)
    k_fill<<<(E + 255) / 256, 256>>>(srcp, dstp, E, N);       // 7

    // ===== Layer 1 gather =====
    {
        int blocks = (N + 7) / 8;                              // 32 lanes/node
        k_gather<DH, 2><<<blocks, 256>>>(nullptr, 0, b1, 1, N);
    }
    // ===== Layer 2 =====
    {
        dim3 grid(DH / 64, mtiles);
        k_gemm_mma<<<grid, 256>>>(nullptr, 0, W2, N, DH);
        int blocks = (N + 7) / 8;
        k_gather<DH, 2><<<blocks, 256>>>(nullptr, 0, b2, 1, N);
    }
    // ===== Layer 3 =====
    {
        dim3 grid(DOUT / 64, mtiles);
        k_gemm_mma<<<grid, 256>>>(nullptr, 0, W3, N, DOUT);
        int blocks = (N + 15) / 16;                            // 16 lanes/node
        k_gather<DOUT, 1><<<blocks, 256>>>((float4*)out, 1, b3, 0, N);
    }
}

// round 9
// speedup vs baseline: 1.1062x; 1.1062x over previous
#include <cuda_runtime.h>
#include <cstdint>

// Problem constants (fixed by the dataset)
#define MAXN   50048
#define MAXE   800000
#define DIN    256
#define DH     256
#define DOUT   64
#define SCAN_B 1024

// Scratch (static device globals — no allocation allowed).
__device__ float g_bufA[MAXN * DH];     // GEMM output (raw XW, no prescale)
__device__ float g_bufB[MAXN * DH];     // aggregation output / next-layer input
__device__ float g_dis[MAXN];           // deg^{-1/2}
__device__ int   g_cnt[MAXN];           // degree count, then fill cursor
__device__ int   g_rowp[MAXN + 1];      // CSR row pointer
__device__ int   g_blk[128];            // block sums for scan
__device__ int   g_csrc[MAXE];          // CSR src indices

__device__ __forceinline__ float tf32_rna(float x) {
    uint32_t r;
    asm("cvt.rna.tf32.f32 %0, %1;" : "=r"(r) : "f"(x));
    return __uint_as_float(r);
}

#define MMA_TF32(D, Ar, Br) \
    asm volatile("mma.sync.aligned.m16n8k8.row.col.f32.tf32.tf32.f32 " \
        "{%0,%1,%2,%3}, {%4,%5,%6,%7}, {%8,%9}, {%0,%1,%2,%3};" \
        : "+f"((D)[0]), "+f"((D)[1]), "+f"((D)[2]), "+f"((D)[3]) \
        : "r"((Ar)[0]), "r"((Ar)[1]), "r"((Ar)[2]), "r"((Ar)[3]), \
          "r"((Br)[0]), "r"((Br)[1]))

// ===========================================================================
// CSR build + normalization (runs on side stream, overlapped with GEMM-1)
// ===========================================================================
__global__ void k_zero_cnt(int n) {
    int i = blockIdx.x * blockDim.x + threadIdx.x;
    if (i < n) g_cnt[i] = 0;
}

__global__ void k_count(const int* __restrict__ dst, int E, int n) {
    int e = blockIdx.x * blockDim.x + threadIdx.x;
    if (e < E) {
        unsigned d = (unsigned)dst[e];
        if (d < (unsigned)n) atomicAdd(&g_cnt[d], 1);
    }
}

// Inclusive scan within blocks; also computes dis = rsqrt(deg+1) (fused).
__global__ void k_scan1(int n) {
    __shared__ int sh[SCAN_B];
    int i = blockIdx.x * SCAN_B + threadIdx.x;
    int v = (i < n) ? g_cnt[i] : 0;
    if (i < n) g_dis[i] = rsqrtf((float)(v + 1));
    sh[threadIdx.x] = v;
    __syncthreads();
    #pragma unroll
    for (int off = 1; off < SCAN_B; off <<= 1) {
        int t = (threadIdx.x >= off) ? sh[threadIdx.x - off] : 0;
        __syncthreads();
        sh[threadIdx.x] += t;
        __syncthreads();
    }
    if (i < n) g_rowp[i + 1] = sh[threadIdx.x];
    if (threadIdx.x == SCAN_B - 1) g_blk[blockIdx.x] = sh[SCAN_B - 1];
}

__global__ void k_scan2(int nb) {
    __shared__ int sh[128];
    int v = (threadIdx.x < nb) ? g_blk[threadIdx.x] : 0;
    sh[threadIdx.x] = v;
    __syncthreads();
    #pragma unroll
    for (int off = 1; off < 128; off <<= 1) {
        int t = (threadIdx.x >= off) ? sh[threadIdx.x - off] : 0;
        __syncthreads();
        sh[threadIdx.x] += t;
        __syncthreads();
    }
    if (threadIdx.x < nb)
        g_blk[threadIdx.x] = (threadIdx.x > 0) ? sh[threadIdx.x - 1] : 0;
}

__global__ void k_scan3(int n) {
    int i = blockIdx.x * blockDim.x + threadIdx.x;
    if (i < n) {
        g_rowp[i + 1] += g_blk[i / SCAN_B];
        g_cnt[i] = 0;
    }
    if (i == 0) g_rowp[0] = 0;
}

__global__ void k_fill(const int* __restrict__ src, const int* __restrict__ dst,
                       int E, int n) {
    int e = blockIdx.x * blockDim.x + threadIdx.x;
    if (e >= E) return;
    unsigned s = (unsigned)src[e];
    unsigned d = (unsigned)dst[e];
    if (s >= (unsigned)n || d >= (unsigned)n) return;
    int pos = g_rowp[d] + atomicAdd(&g_cnt[d], 1);
    if (pos < MAXE) g_csrc[pos] = (int)s;
}

// ===========================================================================
// tf32 mma.sync GEMM: g_bufA[M,Nc] = A[M,256] @ W[256,Nc]   (no prescale)
// Block tile 128 x BN_, 8 warps. BN_=128: warps 2x4 (warp 64x32);
// BN_=64: warps 4x2 (warp 32x32). BK=32, reg double-buffer prefetch.
// ===========================================================================
template <int BN_>
__global__ __launch_bounds__(256) void k_gemm_mma(
    const float* __restrict__ A_ext, int useExt,
    const float* __restrict__ W, int M, int Nc)
{
    const float* __restrict__ A = useExt ? A_ext : (const float*)g_bufB;

    constexpr int WARPS_M = (BN_ == 128) ? 2 : 4;
    constexpr int MT = 8 / WARPS_M;          // 4 or 2 (16-row frags per warp)
    constexpr int NT = 4;                    // 4 x n8 = 32 cols per warp
    constexpr int F4R = BN_ / 4;             // float4 per B row
    constexpr int B_IT = BN_ / 32;           // B load iters per thread

    __shared__ float As[128][40];            // [m][k], pad 8
    __shared__ float Bs[32][BN_ + 8];        // [k][n], pad 8

    const int tid = threadIdx.x;
    const int lane = tid & 31;
    const int wid = tid >> 5;
    const int wm = wid % WARPS_M;
    const int wn = wid / WARPS_M;
    const int gid = lane >> 2;
    const int tig = lane & 3;
    const int rowBase = blockIdx.y * 128;
    const int colBase = blockIdx.x * BN_;

    const int la_row = tid >> 3;             // +32 per i (4 iters)
    const int la_c4  = tid & 7;
    const int lb_k   = tid / F4R;            // +256/F4R per i
    const int lb_c4  = tid % F4R;
    constexpr int LB_STEP = 256 / F4R;

    float acc[MT][NT][4];
    #pragma unroll
    for (int mt = 0; mt < MT; mt++)
        #pragma unroll
        for (int nt = 0; nt < NT; nt++)
            #pragma unroll
            for (int j = 0; j < 4; j++) acc[mt][nt][j] = 0.0f;

    float4 pa[4], pb[B_IT];

    #pragma unroll
    for (int i = 0; i < 4; i++) {
        int grow = rowBase + la_row + i * 32;
        pa[i] = (grow < M) ? ((const float4*)A)[(long long)grow * 64 + la_c4]
                           : make_float4(0.f, 0.f, 0.f, 0.f);
    }
    #pragma unroll
    for (int i = 0; i < B_IT; i++) {
        int k = lb_k + i * LB_STEP;
        pb[i] = *(const float4*)(W + (long long)k * Nc + colBase + lb_c4 * 4);
    }

    #pragma unroll 1
    for (int kb = 0; kb < 8; kb++) {
        #pragma unroll
        for (int i = 0; i < 4; i++) {
            float4 v = pa[i];
            v.x = tf32_rna(v.x); v.y = tf32_rna(v.y);
            v.z = tf32_rna(v.z); v.w = tf32_rna(v.w);
            *(float4*)&As[la_row + i * 32][la_c4 * 4] = v;
        }
        #pragma unroll
        for (int i = 0; i < B_IT; i++) {
            float4 v = pb[i];
            v.x = tf32_rna(v.x); v.y = tf32_rna(v.y);
            v.z = tf32_rna(v.z); v.w = tf32_rna(v.w);
            *(float4*)&Bs[lb_k + i * LB_STEP][lb_c4 * 4] = v;
        }
        __syncthreads();

        if (kb < 7) {
            #pragma unroll
            for (int i = 0; i < 4; i++) {
                int grow = rowBase + la_row + i * 32;
                pa[i] = (grow < M)
                    ? ((const float4*)A)[(long long)grow * 64 + (kb + 1) * 8 + la_c4]
                    : make_float4(0.f, 0.f, 0.f, 0.f);
            }
            #pragma unroll
            for (int i = 0; i < B_IT; i++) {
                int k = (kb + 1) * 32 + lb_k + i * LB_STEP;
                pb[i] = *(const float4*)(W + (long long)k * Nc + colBase + lb_c4 * 4);
            }
        }

        #pragma unroll
        for (int ks = 0; ks < 4; ks++) {
            int k0 = ks * 8;
            uint32_t af[MT][4], bf[NT][2];
            #pragma unroll
            for (int mt = 0; mt < MT; mt++) {
                int m0 = wm * (MT * 16) + mt * 16 + gid;
                af[mt][0] = __float_as_uint(As[m0][k0 + tig]);
                af[mt][1] = __float_as_uint(As[m0 + 8][k0 + tig]);
                af[mt][2] = __float_as_uint(As[m0][k0 + tig + 4]);
                af[mt][3] = __float_as_uint(As[m0 + 8][k0 + tig + 4]);
            }
            #pragma unroll
            for (int nt = 0; nt < NT; nt++) {
                int n0 = wn * 32 + nt * 8 + gid;
                bf[nt][0] = __float_as_uint(Bs[k0 + tig][n0]);
                bf[nt][1] = __float_as_uint(Bs[k0 + tig + 4][n0]);
            }
            #pragma unroll
            for (int mt = 0; mt < MT; mt++)
                #pragma unroll
                for (int nt = 0; nt < NT; nt++)
                    MMA_TF32(acc[mt][nt], af[mt], bf[nt]);
        }
        __syncthreads();
    }

    // Epilogue: plain store (dis scaling moved into gather)
    #pragma unroll
    for (int mt = 0; mt < MT; mt++) {
        int r0 = rowBase + wm * (MT * 16) + mt * 16 + gid;
        int r1 = r0 + 8;
        #pragma unroll
        for (int nt = 0; nt < NT; nt++) {
            int c = colBase + wn * 32 + nt * 8 + tig * 2;
            if (r0 < M)
                *(float2*)(g_bufA + (long long)r0 * Nc + c)
                    = make_float2(acc[mt][nt][0], acc[mt][nt][1]);
            if (r1 < M)
                *(float2*)(g_bufA + (long long)r1 * Nc + c)
                    = make_float2(acc[mt][nt][2], acc[mt][nt][3]);
        }
    }
}

// ===========================================================================
// CSR gather aggregation (fused norm + self-loop + bias + relu):
//   out[i] = dis[i]*( dis[i]*h[i] + sum_s dis[s]*h[s] ) + b
// ===========================================================================
template <int F, int VPT>
__global__ __launch_bounds__(256) void k_gather(
    float4* __restrict__ dst_ext, int useExt,
    const float* __restrict__ bias, int do_relu, int n)
{
    const int L = F / (4 * VPT);                 // lanes per node
    const int F4 = F / 4;
    float4* __restrict__ out = useExt ? dst_ext : (float4*)g_bufB;
    const float4* __restrict__ hs = (const float4*)g_bufA;

    int node = blockIdx.x * (256 / L) + threadIdx.x / L;
    if (node >= n) return;
    int lane = threadIdx.x % L;

    float dd = g_dis[node];
    float4 acc[VPT];
    #pragma unroll
    for (int v = 0; v < VPT; v++) {
        float4 t = hs[(long long)node * F4 + lane + v * L];
        acc[v] = make_float4(t.x * dd, t.y * dd, t.z * dd, t.w * dd);
    }

    int p0 = g_rowp[node], p1 = g_rowp[node + 1];
    int p = p0;
    for (; p + 3 < p1; p += 4) {
        int s0 = g_csrc[p + 0];
        int s1 = g_csrc[p + 1];
        int s2 = g_csrc[p + 2];
        int s3 = g_csrc[p + 3];
        float w0 = g_dis[s0], w1 = g_dis[s1], w2 = g_dis[s2], w3 = g_dis[s3];
        #pragma unroll
        for (int v = 0; v < VPT; v++) {
            float4 t0 = hs[(long long)s0 * F4 + lane + v * L];
            float4 t1 = hs[(long long)s1 * F4 + lane + v * L];
            float4 t2 = hs[(long long)s2 * F4 + lane + v * L];
            float4 t3 = hs[(long long)s3 * F4 + lane + v * L];
            acc[v].x += (t0.x * w0 + t1.x * w1) + (t2.x * w2 + t3.x * w3);
            acc[v].y += (t0.y * w0 + t1.y * w1) + (t2.y * w2 + t3.y * w3);
            acc[v].z += (t0.z * w0 + t1.z * w1) + (t2.z * w2 + t3.z * w3);
            acc[v].w += (t0.w * w0 + t1.w * w1) + (t2.w * w2 + t3.w * w3);
        }
    }
    for (; p < p1; p++) {
        int s = g_csrc[p];
        float w = g_dis[s];
        #pragma unroll
        for (int v = 0; v < VPT; v++) {
            float4 t = hs[(long long)s * F4 + lane + v * L];
            acc[v].x += t.x * w; acc[v].y += t.y * w;
            acc[v].z += t.z * w; acc[v].w += t.w * w;
        }
    }

    #pragma unroll
    for (int v = 0; v < VPT; v++) {
        float4 b4 = ((const float4*)bias)[lane + v * L];
        float4 o;
        o.x = acc[v].x * dd + b4.x;
        o.y = acc[v].y * dd + b4.y;
        o.z = acc[v].z * dd + b4.z;
        o.w = acc[v].w * dd + b4.w;
        if (do_relu) {
            o.x = fmaxf(o.x, 0.0f); o.y = fmaxf(o.y, 0.0f);
            o.z = fmaxf(o.z, 0.0f); o.w = fmaxf(o.w, 0.0f);
        }
        out[(long long)node * F4 + lane + v * L] = o;
    }
}

// ===========================================================================
// Launch: CSR build forked to a side stream, overlapped with layer-1 GEMM.
// ===========================================================================
extern "C" void kernel_launch(void* const* d_in, const int* in_sizes, int n_in,
                              void* d_out, int out_size)
{
    const float* x   = (const float*)d_in[0];
    const int*   ei  = (const int*)d_in[1];
    const float* W1  = (const float*)d_in[2];
    const float* b1  = (const float*)d_in[3];
    const float* W2  = (const float*)d_in[4];
    const float* b2  = (const float*)d_in[5];
    const float* W3  = (const float*)d_in[6];
    const float* b3  = (const float*)d_in[7];
    float*       out = (float*)d_out;

    const int N = in_sizes[0] / DIN;
    const int E = in_sizes[1] / 2;
    const int* srcp = ei;
    const int* dstp = ei + E;

    int mtiles = (N + 127) / 128;
    int nb = (N + SCAN_B - 1) / SCAN_B;

    // One-time resource creation (no device memory; work per call is identical)
    static cudaStream_t s2 = nullptr;
    static cudaEvent_t evF = nullptr, evJ = nullptr;
    if (!s2) {
        cudaStreamCreateWithFlags(&s2, cudaStreamNonBlocking);
        cudaEventCreateWithFlags(&evF, cudaEventDisableTiming);
        cudaEventCreateWithFlags(&evJ, cudaEventDisableTiming);
    }

    // Fork: CSR build chain on side stream
    cudaEventRecord(evF, 0);
    cudaStreamWaitEvent(s2, evF, 0);
    k_zero_cnt<<<(N + 255) / 256, 256, 0, s2>>>(N);
    k_count<<<(E + 255) / 256, 256, 0, s2>>>(dstp, E, N);
    k_scan1<<<nb, SCAN_B, 0, s2>>>(N);
    k_scan2<<<1, 128, 0, s2>>>(nb);
    k_scan3<<<(N + 255) / 256, 256, 0, s2>>>(N);
    k_fill<<<(E + 255) / 256, 256, 0, s2>>>(srcp, dstp, E, N);
    cudaEventRecord(evJ, s2);

    // Main stream: layer-1 GEMM (independent of CSR/dis now)
    {
        dim3 grid(DH / 128, mtiles);
        k_gemm_mma<128><<<grid, 256>>>(x, 1, W1, N, DH);
    }
    // Join: gather needs CSR + dis
    cudaStreamWaitEvent(0, evJ, 0);

    // ===== Layer 1 gather =====
    k_gather<DH, 2><<<(N + 7) / 8, 256>>>(nullptr, 0, b1, 1, N);

    // ===== Layer 2 =====
    {
        dim3 grid(DH / 128, mtiles);
        k_gemm_mma<128><<<grid, 256>>>(nullptr, 0, W2, N, DH);
        k_gather<DH, 2><<<(N + 7) / 8, 256>>>(nullptr, 0, b2, 1, N);
    }
    // ===== Layer 3 =====
    {
        dim3 grid(DOUT / 64, mtiles);
        k_gemm_mma<64><<<grid, 256>>>(nullptr, 0, W3, N, DOUT);
        k_gather<DOUT, 1><<<(N + 15) / 16, 256>>>((float4*)out, 1, b3, 0, N);
    }
}